// round 1
// baseline (speedup 1.0000x reference)
#include <cuda_runtime.h>
#include <cstdint>

#define N_TOTAL 100000
#define DIM     128
#define N_USER  50000

// 51.2 MB scratch accumulator for LI_side_embed (user rows 0..49999, item rows 50000..99999)
__device__ float g_li[(size_t)N_TOTAL * DIM];

// ---------------------------------------------------------------------------
// Zero the accumulator (float4 stores, one element per thread)
// ---------------------------------------------------------------------------
__global__ void zero_li_kernel() {
    int i = blockIdx.x * blockDim.x + threadIdx.x;
    float4* p = reinterpret_cast<float4*>(g_li);
    const int n4 = (N_TOTAL * DIM) / 4;  // 3.2M
    if (i < n4) p[i] = make_float4(0.f, 0.f, 0.f, 0.f);
}

// ---------------------------------------------------------------------------
// COO scatter: one warp per edge.
// li[row_offset + rows[e]] += vals[e] * ebs[cols[e]]
// Each lane handles one float4 (4 of the 128 dims) -> 1 LDG.128 + 1 RED.128.
// ---------------------------------------------------------------------------
__global__ void scatter_kernel(const int*   __restrict__ rows,
                               const int*   __restrict__ cols,
                               const float* __restrict__ vals,
                               const float* __restrict__ ebs,
                               int row_offset, int E) {
    int gwid = (blockIdx.x * blockDim.x + threadIdx.x) >> 5;
    int lane = threadIdx.x & 31;
    if (gwid >= E) return;

    int   r = __ldg(rows + gwid);
    int   c = __ldg(cols + gwid);
    float v = __ldg(vals + gwid);

    const float4* src = reinterpret_cast<const float4*>(ebs + (size_t)c * DIM);
    float4 e = src[lane];
    float4 m = make_float4(e.x * v, e.y * v, e.z * v, e.w * v);

    float4* dst = reinterpret_cast<float4*>(g_li + (size_t)(row_offset + r) * DIM);
    atomicAdd(dst + lane, m);   // vector f32 atomic (sm_90+)
}

// ---------------------------------------------------------------------------
// out[row] = relu(li[row_offset + row] @ W)  for row in [0, M)
// Tiled SGEMM: block = 256 threads, tile 64 rows x 128 cols, BK = 8.
// Thread (ty,tx) computes a 4x8 register tile.
// ---------------------------------------------------------------------------
__global__ void gemm_relu_kernel(const float* __restrict__ W,
                                 float*       __restrict__ out,
                                 int row_offset, int M) {
    __shared__ float As[8][72];    // [k][row], padded: row stride 72 floats (16B-aligned)
    __shared__ float Ws[8][128];   // [k][col]

    const float* A = g_li + (size_t)row_offset * DIM;

    int tid = threadIdx.x;
    int tx  = tid & 15;            // col group: cols tx*8 .. tx*8+7
    int ty  = tid >> 4;            // row group: rows ty*4 .. ty*4+3
    int rowBase = blockIdx.x * 64;

    float acc[4][8];
#pragma unroll
    for (int i = 0; i < 4; i++)
#pragma unroll
        for (int j = 0; j < 8; j++) acc[i][j] = 0.f;

    for (int kk = 0; kk < 128; kk += 8) {
        // Load A tile (64 rows x 8 k), store transposed As[k][row].
        if (tid < 128) {
            int r = tid >> 1, q = tid & 1;
            int row = rowBase + r;
            float4 a = make_float4(0.f, 0.f, 0.f, 0.f);
            if (row < M)
                a = *reinterpret_cast<const float4*>(A + (size_t)row * DIM + kk + q * 4);
            As[q * 4 + 0][r] = a.x;
            As[q * 4 + 1][r] = a.y;
            As[q * 4 + 2][r] = a.z;
            As[q * 4 + 3][r] = a.w;
        }
        // Load W tile (8 k x 128 cols), one float4 per thread, coalesced.
        {
            int k = tid >> 5, c4 = tid & 31;
            float4 w = *reinterpret_cast<const float4*>(W + (size_t)(kk + k) * DIM + c4 * 4);
            *reinterpret_cast<float4*>(&Ws[k][c4 * 4]) = w;
        }
        __syncthreads();

#pragma unroll
        for (int k = 0; k < 8; k++) {
            float4 a  = *reinterpret_cast<const float4*>(&As[k][ty * 4]);
            float4 w0 = *reinterpret_cast<const float4*>(&Ws[k][tx * 8]);
            float4 w1 = *reinterpret_cast<const float4*>(&Ws[k][tx * 8 + 4]);
            float av[4] = {a.x, a.y, a.z, a.w};
            float wv[8] = {w0.x, w0.y, w0.z, w0.w, w1.x, w1.y, w1.z, w1.w};
#pragma unroll
            for (int i = 0; i < 4; i++)
#pragma unroll
                for (int j = 0; j < 8; j++)
                    acc[i][j] = fmaf(av[i], wv[j], acc[i][j]);
        }
        __syncthreads();
    }

    // Store with ReLU (out is row-major [*, 128]; this kernel writes rows rowBase..rowBase+63)
#pragma unroll
    for (int i = 0; i < 4; i++) {
        int row = rowBase + ty * 4 + i;
        if (row < M) {
            float4 o0, o1;
            o0.x = fmaxf(acc[i][0], 0.f);
            o0.y = fmaxf(acc[i][1], 0.f);
            o0.z = fmaxf(acc[i][2], 0.f);
            o0.w = fmaxf(acc[i][3], 0.f);
            o1.x = fmaxf(acc[i][4], 0.f);
            o1.y = fmaxf(acc[i][5], 0.f);
            o1.z = fmaxf(acc[i][6], 0.f);
            o1.w = fmaxf(acc[i][7], 0.f);
            *reinterpret_cast<float4*>(out + (size_t)row * DIM + tx * 8)     = o0;
            *reinterpret_cast<float4*>(out + (size_t)row * DIM + tx * 8 + 4) = o1;
        }
    }
}

// ---------------------------------------------------------------------------
// Inputs (metadata order):
//  0: ebs        [100000,128] f32
//  1: rows_user  [800000]     i32
//  2: cols_user  [800000]     i32
//  3: vals_user  [800000]     f32
//  4: W_side_user[128,128]    f32
//  5: rows_item  [800000]     i32
//  6: cols_item  [800000]     i32
//  7: vals_item  [800000]     f32
//  8: W_side_item[128,128]    f32
// Output: [100000,128] f32 (user fold rows 0..49999, item fold rows 50000..99999)
// ---------------------------------------------------------------------------
extern "C" void kernel_launch(void* const* d_in, const int* in_sizes, int n_in,
                              void* d_out, int out_size) {
    const float* ebs    = (const float*)d_in[0];
    const int*   rows_u = (const int*)  d_in[1];
    const int*   cols_u = (const int*)  d_in[2];
    const float* vals_u = (const float*)d_in[3];
    const float* W_u    = (const float*)d_in[4];
    const int*   rows_i = (const int*)  d_in[5];
    const int*   cols_i = (const int*)  d_in[6];
    const float* vals_i = (const float*)d_in[7];
    const float* W_i    = (const float*)d_in[8];
    float* out = (float*)d_out;

    int E_u = in_sizes[1];
    int E_i = in_sizes[5];

    // 1) zero the accumulator
    {
        int n4 = (N_TOTAL * DIM) / 4;
        int threads = 256;
        int blocks = (n4 + threads - 1) / threads;
        zero_li_kernel<<<blocks, threads>>>();
    }

    // 2) scatter (one warp per edge, 8 warps per block)
    {
        int threads = 256;
        int blocks_u = (E_u + 7) / 8;
        int blocks_i = (E_i + 7) / 8;
        scatter_kernel<<<blocks_u, threads>>>(rows_u, cols_u, vals_u, ebs, 0,      E_u);
        scatter_kernel<<<blocks_i, threads>>>(rows_i, cols_i, vals_i, ebs, N_USER, E_i);
    }

    // 3) GEMM + ReLU
    {
        int threads = 256;
        int blocks = (N_USER + 63) / 64;  // 782
        gemm_relu_kernel<<<blocks, threads>>>(W_u, out,                          0,      N_USER);
        gemm_relu_kernel<<<blocks, threads>>>(W_i, out + (size_t)N_USER * DIM,   N_USER, N_TOTAL - N_USER);
    }
}

// round 2
// speedup vs baseline: 1.1805x; 1.1805x over previous
#include <cuda_runtime.h>
#include <cstdint>

#define N_TOTAL 100000
#define DIM     128
#define N_USER  50000
#define M_ENT   50000
#define GEMM_BLOCKS_PER_ENT 391   // ceil(50000/128)

// 51.2 MB scratch accumulator for LI_side_embed (user rows 0..49999, item rows 50000..99999)
__device__ float g_li[(size_t)N_TOTAL * DIM];

// ---------------------------------------------------------------------------
// Zero the accumulator
// ---------------------------------------------------------------------------
__global__ void zero_li_kernel() {
    int i = blockIdx.x * blockDim.x + threadIdx.x;
    float4* p = reinterpret_cast<float4*>(g_li);
    const int n4 = (N_TOTAL * DIM) / 4;
    if (i < n4) p[i] = make_float4(0.f, 0.f, 0.f, 0.f);
}

// ---------------------------------------------------------------------------
// COO scatter, both entities in one launch: one warp per edge.
// li[row_offset + rows[e]] += vals[e] * ebs[cols[e]]
// ---------------------------------------------------------------------------
__global__ void scatter_kernel(const int*   __restrict__ rows_u,
                               const int*   __restrict__ cols_u,
                               const float* __restrict__ vals_u,
                               const int*   __restrict__ rows_i,
                               const int*   __restrict__ cols_i,
                               const float* __restrict__ vals_i,
                               const float* __restrict__ ebs,
                               int E_u, int E_i) {
    int gwid = (blockIdx.x * blockDim.x + threadIdx.x) >> 5;
    int lane = threadIdx.x & 31;

    const int* rows; const int* cols; const float* vals;
    int row_offset, e;
    if (gwid < E_u) {
        rows = rows_u; cols = cols_u; vals = vals_u; row_offset = 0; e = gwid;
    } else {
        e = gwid - E_u;
        if (e >= E_i) return;
        rows = rows_i; cols = cols_i; vals = vals_i; row_offset = N_USER;
    }

    int   r = __ldg(rows + e);
    int   c = __ldg(cols + e);
    float v = __ldg(vals + e);

    const float4* src = reinterpret_cast<const float4*>(ebs + (size_t)c * DIM);
    float4 ev = src[lane];
    float4 m = make_float4(ev.x * v, ev.y * v, ev.z * v, ev.w * v);

    float4* dst = reinterpret_cast<float4*>(g_li + (size_t)(row_offset + r) * DIM);
    atomicAdd(dst + lane, m);   // vector f32 atomic (sm_90+)
}

// ---------------------------------------------------------------------------
// Fused GEMM+ReLU for both entities, one launch.
// out[row] = relu(li[row] @ W_entity), BM=128, BN=128 (full), BK=8,
// 256 threads, 8x8 register tile per thread, double-buffered smem.
// ---------------------------------------------------------------------------
__global__ __launch_bounds__(256, 2)
void gemm_relu_kernel(const float* __restrict__ Wu,
                      const float* __restrict__ Wi,
                      float*       __restrict__ out) {
    __shared__ float As[2][8][128];   // [buf][k][row]
    __shared__ float Ws[2][8][128];   // [buf][k][col]

    int b = blockIdx.x;
    int entity = (b >= GEMM_BLOCKS_PER_ENT) ? 1 : 0;
    const float* W = entity ? Wi : Wu;
    int rowBase = (b - entity * GEMM_BLOCKS_PER_ENT) * 128;
    const float* A = g_li + (size_t)(entity ? N_USER : 0) * DIM;
    float* O = out + (size_t)(entity ? N_USER : 0) * DIM;

    int tid = threadIdx.x;
    // A tile load: row = tid>>1 (0..127), k-quad = (tid&1)*4
    int arow = tid >> 1;
    int akq  = (tid & 1) * 4;
    int agrow = rowBase + arow;
    bool avalid = (agrow < M_ENT);
    const float* aptr = A + (size_t)agrow * DIM + akq;   // + kk each tile
    // W tile load: k = tid>>5 (0..7), col = (tid&31)*4
    int wk = tid >> 5;
    int wc = (tid & 31) * 4;
    const float* wptr = W + (size_t)wk * DIM + wc;       // + kk*DIM each tile

    int tx = tid & 15;   // col group: cols tx*8..tx*8+7
    int ty = tid >> 4;   // row group: rows ty*8..ty*8+7

    float acc[8][8];
#pragma unroll
    for (int i = 0; i < 8; i++)
#pragma unroll
        for (int j = 0; j < 8; j++) acc[i][j] = 0.f;

    // --- load first tile (kk = 0) into buf 0 ---
    {
        float4 a = avalid ? *reinterpret_cast<const float4*>(aptr)
                          : make_float4(0.f, 0.f, 0.f, 0.f);
        As[0][akq + 0][arow] = a.x;
        As[0][akq + 1][arow] = a.y;
        As[0][akq + 2][arow] = a.z;
        As[0][akq + 3][arow] = a.w;
        float4 w = *reinterpret_cast<const float4*>(wptr);
        *reinterpret_cast<float4*>(&Ws[0][wk][wc]) = w;
    }
    __syncthreads();

    int buf = 0;
#pragma unroll
    for (int t = 0; t < 16; t++) {
        // prefetch next tile into the other buffer
        if (t < 15) {
            int kk = (t + 1) * 8;
            float4 a = avalid ? *reinterpret_cast<const float4*>(aptr + kk)
                              : make_float4(0.f, 0.f, 0.f, 0.f);
            float4 w = *reinterpret_cast<const float4*>(wptr + (size_t)kk * DIM);
            int nb = buf ^ 1;
            As[nb][akq + 0][arow] = a.x;
            As[nb][akq + 1][arow] = a.y;
            As[nb][akq + 2][arow] = a.z;
            As[nb][akq + 3][arow] = a.w;
            *reinterpret_cast<float4*>(&Ws[nb][wk][wc]) = w;
        }

        // compute on current buffer
#pragma unroll
        for (int k = 0; k < 8; k++) {
            float4 a0 = *reinterpret_cast<const float4*>(&As[buf][k][ty * 8]);
            float4 a1 = *reinterpret_cast<const float4*>(&As[buf][k][ty * 8 + 4]);
            float4 w0 = *reinterpret_cast<const float4*>(&Ws[buf][k][tx * 8]);
            float4 w1 = *reinterpret_cast<const float4*>(&Ws[buf][k][tx * 8 + 4]);
            float av[8] = {a0.x, a0.y, a0.z, a0.w, a1.x, a1.y, a1.z, a1.w};
            float wv[8] = {w0.x, w0.y, w0.z, w0.w, w1.x, w1.y, w1.z, w1.w};
#pragma unroll
            for (int i = 0; i < 8; i++)
#pragma unroll
                for (int j = 0; j < 8; j++)
                    acc[i][j] = fmaf(av[i], wv[j], acc[i][j]);
        }
        __syncthreads();
        buf ^= 1;
    }

    // epilogue: ReLU + store
#pragma unroll
    for (int i = 0; i < 8; i++) {
        int row = rowBase + ty * 8 + i;
        if (row < M_ENT) {
            float4 o0, o1;
            o0.x = fmaxf(acc[i][0], 0.f);
            o0.y = fmaxf(acc[i][1], 0.f);
            o0.z = fmaxf(acc[i][2], 0.f);
            o0.w = fmaxf(acc[i][3], 0.f);
            o1.x = fmaxf(acc[i][4], 0.f);
            o1.y = fmaxf(acc[i][5], 0.f);
            o1.z = fmaxf(acc[i][6], 0.f);
            o1.w = fmaxf(acc[i][7], 0.f);
            *reinterpret_cast<float4*>(O + (size_t)row * DIM + tx * 8)     = o0;
            *reinterpret_cast<float4*>(O + (size_t)row * DIM + tx * 8 + 4) = o1;
        }
    }
}

// ---------------------------------------------------------------------------
extern "C" void kernel_launch(void* const* d_in, const int* in_sizes, int n_in,
                              void* d_out, int out_size) {
    const float* ebs    = (const float*)d_in[0];
    const int*   rows_u = (const int*)  d_in[1];
    const int*   cols_u = (const int*)  d_in[2];
    const float* vals_u = (const float*)d_in[3];
    const float* W_u    = (const float*)d_in[4];
    const int*   rows_i = (const int*)  d_in[5];
    const int*   cols_i = (const int*)  d_in[6];
    const float* vals_i = (const float*)d_in[7];
    const float* W_i    = (const float*)d_in[8];
    float* out = (float*)d_out;

    int E_u = in_sizes[1];
    int E_i = in_sizes[5];

    // 1) zero accumulator
    {
        int n4 = (N_TOTAL * DIM) / 4;
        zero_li_kernel<<<(n4 + 255) / 256, 256>>>();
    }

    // 2) scatter, both entities in one launch (8 warps / block)
    {
        int total_warps = E_u + E_i;
        int blocks = (total_warps + 7) / 8;
        scatter_kernel<<<blocks, 256>>>(rows_u, cols_u, vals_u,
                                        rows_i, cols_i, vals_i,
                                        ebs, E_u, E_i);
    }

    // 3) fused GEMM + ReLU, both entities in one launch
    gemm_relu_kernel<<<2 * GEMM_BLOCKS_PER_ENT, 256>>>(W_u, W_i, out);
}